// round 8
// baseline (speedup 1.0000x reference)
#include <cuda_runtime.h>
#include <cuda_fp16.h>
#include <cstdint>

#define N_NODES 100000
#define HIDDEN  128
#define NPB     256   // nodes per CTA in GEMM kernel
#define CAP     48    // per-node edge bin capacity (Poisson mean 16; P(>=48)~1e-10)

// Scratch (device globals — allocation-free rule).
// INVARIANT: g_cnt[] and g_ovf_cnt are ZERO at kernel_launch entry
// (zero-init at module load; g_cnt re-zeroed inside k_gather_final,
//  g_ovf_cnt reset by k_fix).
__device__ __align__(16) float   g_S  [(size_t)N_NODES * HIDDEN];
__device__ __align__(16) float   g_I  [(size_t)N_NODES * HIDDEN];
__device__ __align__(16) __half2 g_Ih [(size_t)N_NODES * (HIDDEN / 2)];
__device__ int   g_cnt[N_NODES];
__device__ int   g_bin[(size_t)N_NODES * CAP];
__device__ int   g_ovf_cnt;
__device__ int   g_ovf[2 * 1600000];

__device__ __forceinline__ float sigmoidf(float v) {
    return 1.f / (1.f + __expf(-v));
}
__device__ __forceinline__ uint32_t to_tf32(float f) {
    uint32_t u;
    asm("cvt.rna.tf32.f32 %0, %1;" : "=r"(u) : "f"(f));
    return u;
}
__device__ __forceinline__ void mma_tf32(float* c, uint32_t a0, uint32_t a1,
                                         uint32_t a2, uint32_t a3,
                                         uint32_t b0, uint32_t b1) {
    asm volatile(
        "mma.sync.aligned.m16n8k8.row.col.f32.tf32.tf32.f32 "
        "{%0,%1,%2,%3}, {%4,%5,%6,%7}, {%8,%9}, {%0,%1,%2,%3};"
        : "+f"(c[0]), "+f"(c[1]), "+f"(c[2]), "+f"(c[3])
        : "r"(a0), "r"(a1), "r"(a2), "r"(a3), "r"(b0), "r"(b1));
}

// Shared layout (uint32 elements):
//   xs [256][132]  node-major tf32 x tile
//   Ws [128][132]  o-major tf32 W   (col-major B for mma: B[n][k])
//   sgam[256], sbias[128] as floats
#define XS_SZ   (256 * 132)
#define WS_SZ   (128 * 132)
#define SM_U32  (XS_SZ + WS_SZ + 256 + 128)

// ---------------------------------------------------------------------------
// K1: tf32 mma.sync sigmoid-GEMM. 512 threads = 16 warps; warp w computes
// nodes [w*16, w*16+16) x all 128 outputs, K=128 in 16 k-steps.
// Fuses: g_S, g_I (fp32), g_Ih (fp16 mirror), out[2] = gamma*I, out[3] = 0.
// ---------------------------------------------------------------------------
__global__ __launch_bounds__(512, 1) void k_gemm(
    const float* __restrict__ x, const float* __restrict__ W,
    const float* __restrict__ b, float* __restrict__ out)
{
    extern __shared__ uint32_t sh[];
    uint32_t* xs    = sh;
    uint32_t* Ws    = sh + XS_SZ;
    float*    sgam  = reinterpret_cast<float*>(sh + XS_SZ + WS_SZ);
    float*    sbias = sgam + 256;

    const int tid  = threadIdx.x;
    const int warp = tid >> 5;
    const int lane = tid & 31;
    const int grp  = lane >> 2;   // 0..7
    const int qk   = lane & 3;    // 0..3
    const int base = blockIdx.x * NPB;
    const int nn   = min(NPB, N_NODES - base);
    const int m0   = warp * 16;

    // Ws[o*132 + h] = tf32(W[o*128 + h])   — float4 LDG, uint4 STS
    {
        const float4* Wsrc = reinterpret_cast<const float4*>(W);
        for (int idx = tid; idx < HIDDEN * 32; idx += 512) {
            const int o = idx >> 5, q = idx & 31;
            const float4 v = Wsrc[idx];
            uint4 u;
            u.x = to_tf32(v.x); u.y = to_tf32(v.y);
            u.z = to_tf32(v.z); u.w = to_tf32(v.w);
            *reinterpret_cast<uint4*>(&Ws[o * 132 + q * 4]) = u;
        }
    }
    if (tid < HIDDEN) sbias[tid] = b[tid];
    // gamma = x[3, node, 1]
    for (int n = tid; n < NPB; n += 512) {
        sgam[n] = (n < nn)
            ? x[((size_t)3 * N_NODES + base + n) * HIDDEN + 1] : 0.f;
    }

    for (int s = 0; s < 2; ++s) {
        // xs[n*132 + h] = tf32(x[s, base+n, h]); rows >= nn read the next
        // s-slice (in-bounds of x, results discarded).
        const float4* xsrc = reinterpret_cast<const float4*>(
            x + ((size_t)s * N_NODES + base) * HIDDEN);
        __syncthreads();   // previous-iter consumers done before overwrite
        for (int idx = tid; idx < NPB * 32; idx += 512) {
            const int n = idx >> 5, q = idx & 31;
            const float4 v = xsrc[idx];
            uint4 u;
            u.x = to_tf32(v.x); u.y = to_tf32(v.y);
            u.z = to_tf32(v.z); u.w = to_tf32(v.w);
            *reinterpret_cast<uint4*>(&xs[n * 132 + q * 4]) = u;
        }
        __syncthreads();

        float acc[16][4];
        #pragma unroll
        for (int nb = 0; nb < 16; ++nb)
            #pragma unroll
            for (int i = 0; i < 4; ++i) acc[nb][i] = 0.f;

        const uint32_t* xrow0 = xs + (m0 + grp) * 132;       // rows m0+grp
        const uint32_t* xrow1 = xrow0 + 8 * 132;             // rows m0+grp+8

        #pragma unroll 2
        for (int k0 = 0; k0 < 16; ++k0) {
            const int kb = k0 * 8;
            const uint32_t a0 = xrow0[kb + qk];
            const uint32_t a1 = xrow1[kb + qk];
            const uint32_t a2 = xrow0[kb + qk + 4];
            const uint32_t a3 = xrow1[kb + qk + 4];
            #pragma unroll
            for (int nb = 0; nb < 16; ++nb) {
                const uint32_t* wrow = Ws + (nb * 8 + grp) * 132 + kb;
                mma_tf32(acc[nb], a0, a1, a2, a3, wrow[qk], wrow[qk + 4]);
            }
        }

        // Epilogue: thread owns rows r0 = m0+grp, r1 = r0+8;
        // per nb, cols nb*8 + 2*qk (+1).
        const int r0 = m0 + grp, r1 = r0 + 8;
        const float gm0 = sgam[r0], gm1 = sgam[r1];
        #pragma unroll
        for (int nb = 0; nb < 16; ++nb) {
            const int col = nb * 8 + 2 * qk;
            const float b0 = sbias[col], b1 = sbias[col + 1];
            const float v00 = sigmoidf(acc[nb][0] + b0);
            const float v01 = sigmoidf(acc[nb][1] + b1);
            const float v10 = sigmoidf(acc[nb][2] + b0);
            const float v11 = sigmoidf(acc[nb][3] + b1);
            const size_t o0 = ((size_t)(base + r0)) * HIDDEN + col;
            const size_t o1 = ((size_t)(base + r1)) * HIDDEN + col;
            if (s == 0) {
                if (r0 < nn) *reinterpret_cast<float2*>(&g_S[o0]) = make_float2(v00, v01);
                if (r1 < nn) *reinterpret_cast<float2*>(&g_S[o1]) = make_float2(v10, v11);
            } else {
                if (r0 < nn) {
                    *reinterpret_cast<float2*>(&g_I[o0]) = make_float2(v00, v01);
                    g_Ih[((size_t)(base + r0)) * 64 + nb * 4 + qk]
                        = __floats2half2_rn(v00, v01);
                    *reinterpret_cast<float2*>(&out[(size_t)2 * N_NODES * HIDDEN + o0])
                        = make_float2(gm0 * v00, gm0 * v01);
                    *reinterpret_cast<float2*>(&out[(size_t)3 * N_NODES * HIDDEN + o0])
                        = make_float2(0.f, 0.f);
                }
                if (r1 < nn) {
                    *reinterpret_cast<float2*>(&g_I[o1]) = make_float2(v10, v11);
                    g_Ih[((size_t)(base + r1)) * 64 + nb * 4 + qk]
                        = __floats2half2_rn(v10, v11);
                    *reinterpret_cast<float2*>(&out[(size_t)2 * N_NODES * HIDDEN + o1])
                        = make_float2(gm1 * v10, gm1 * v11);
                    *reinterpret_cast<float2*>(&out[(size_t)3 * N_NODES * HIDDEN + o1])
                        = make_float2(0.f, 0.f);
                }
            }
        }
    }
}

// ---------------------------------------------------------------------------
// K2: bin edges by destination row (indices are int32 per JAX default x64-off).
// ---------------------------------------------------------------------------
__global__ __launch_bounds__(256) void k_place(
    const int* __restrict__ rows, const int* __restrict__ cols, int n_edges)
{
    const int i = blockIdx.x * 256 + threadIdx.x;
    if (i >= n_edges) return;
    int r = rows[i], c = cols[i];
    r = min(max(r, 0), N_NODES - 1);
    c = min(max(c, 0), N_NODES - 1);
    const int slot = atomicAdd(&g_cnt[r], 1);
    if (slot < CAP) {
        g_bin[(size_t)r * CAP + slot] = c;
    } else {
        const int o = atomicAdd(&g_ovf_cnt, 1);
        g_ovf[2 * o] = r;
        g_ovf[2 * o + 1] = c;
    }
}

// ---------------------------------------------------------------------------
// K3: gather + finalize. Warp per node, fp16 I-rows (256B each), MLP=8:
//     AI = sum I[col];  dS = -beta*AI*S ; dI = -dS - gamma*I.
//     Lane covers cols [lane*4, lane*4+4) (uint2 = 2x half2 = 4 halves).
//     Also re-zeroes g_cnt[node] for the next call.
// ---------------------------------------------------------------------------
__global__ __launch_bounds__(256) void k_gather_final(
    const float* __restrict__ x, float* __restrict__ out)
{
    const int node = (blockIdx.x * 256 + threadIdx.x) >> 5;
    if (node >= N_NODES) return;
    const int lane = threadIdx.x & 31;

    const int d = min(g_cnt[node], CAP);
    if (lane == 0) g_cnt[node] = 0;   // reset for next call/replay
    const int* __restrict__ bin = g_bin + (size_t)node * CAP;
    const uint2* __restrict__ Ih = reinterpret_cast<const uint2*>(g_Ih);

    float4 a = make_float4(0.f, 0.f, 0.f, 0.f);
    int i = 0;
    for (; i + 8 <= d; i += 8) {      // 8 outstanding 256B L2 loads per warp
        int c[8];
        #pragma unroll
        for (int k = 0; k < 8; ++k) c[k] = __ldg(&bin[i + k]);
        uint2 u[8];
        #pragma unroll
        for (int k = 0; k < 8; ++k) u[k] = Ih[(size_t)c[k] * 32 + lane];
        #pragma unroll
        for (int k = 0; k < 8; ++k) {
            const float2 f0 = __half22float2(*reinterpret_cast<__half2*>(&u[k].x));
            const float2 f1 = __half22float2(*reinterpret_cast<__half2*>(&u[k].y));
            a.x += f0.x; a.y += f0.y; a.z += f1.x; a.w += f1.y;
        }
    }
    if (i + 4 <= d) {
        int c[4];
        #pragma unroll
        for (int k = 0; k < 4; ++k) c[k] = __ldg(&bin[i + k]);
        uint2 u[4];
        #pragma unroll
        for (int k = 0; k < 4; ++k) u[k] = Ih[(size_t)c[k] * 32 + lane];
        #pragma unroll
        for (int k = 0; k < 4; ++k) {
            const float2 f0 = __half22float2(*reinterpret_cast<__half2*>(&u[k].x));
            const float2 f1 = __half22float2(*reinterpret_cast<__half2*>(&u[k].y));
            a.x += f0.x; a.y += f0.y; a.z += f1.x; a.w += f1.y;
        }
        i += 4;
    }
    for (; i < d; ++i) {
        const uint2 u = Ih[(size_t)__ldg(&bin[i]) * 32 + lane];
        const float2 f0 = __half22float2(*reinterpret_cast<__half2*>(
            const_cast<unsigned*>(&u.x)));
        const float2 f1 = __half22float2(*reinterpret_cast<__half2*>(
            const_cast<unsigned*>(&u.y)));
        a.x += f0.x; a.y += f0.y; a.z += f1.x; a.w += f1.y;
    }

    const float beta = x[((size_t)3 * N_NODES + node) * HIDDEN];
    const size_t fo = (size_t)node * 32 + lane;
    const float4 S4 = reinterpret_cast<const float4*>(g_S)[fo];
    const float4 G4 = reinterpret_cast<const float4*>(
        out + (size_t)2 * N_NODES * HIDDEN)[fo];

    float4 dS, dI;
    dS.x = -beta * a.x * S4.x;  dI.x = -dS.x - G4.x;
    dS.y = -beta * a.y * S4.y;  dI.y = -dS.y - G4.y;
    dS.z = -beta * a.z * S4.z;  dI.z = -dS.z - G4.z;
    dS.w = -beta * a.w * S4.w;  dI.w = -dS.w - G4.w;

    reinterpret_cast<float4*>(out)[fo] = dS;
    reinterpret_cast<float4*>(out + (size_t)N_NODES * HIDDEN)[fo] = dI;
}

// ---------------------------------------------------------------------------
// K4: overflow fix-up (expected empty; uses fp32 g_I for full precision)
//     + reset g_ovf_cnt for the next call.
// ---------------------------------------------------------------------------
__global__ __launch_bounds__(256) void k_fix(
    const float* __restrict__ x, float* __restrict__ out)
{
    const int n = g_ovf_cnt;
    if (n > 0) {
        const long long total = (long long)n * HIDDEN;
        const int stride = gridDim.x * 256;
        for (long long idx = blockIdx.x * 256 + threadIdx.x; idx < total;
             idx += stride) {
            const int e = (int)(idx >> 7);
            const int j = (int)(idx & 127);
            const int r = g_ovf[2 * e];
            const int c = g_ovf[2 * e + 1];
            const float v = g_I[(size_t)c * HIDDEN + j];
            const float beta = x[((size_t)3 * N_NODES + r) * HIDDEN];
            const float delta = -beta * v * g_S[(size_t)r * HIDDEN + j];
            atomicAdd(&out[(size_t)r * HIDDEN + j], delta);
            atomicAdd(&out[(size_t)N_NODES * HIDDEN + (size_t)r * HIDDEN + j], -delta);
        }
    }
    if (blockIdx.x == 0 && threadIdx.x == 0) g_ovf_cnt = 0;
}

// ---------------------------------------------------------------------------
extern "C" void kernel_launch(void* const* d_in, const int* in_sizes, int n_in,
                              void* d_out, int out_size)
{
    const float* x    = (const float*)d_in[0];
    const float* W    = (const float*)d_in[1];
    const float* b    = (const float*)d_in[2];
    const int*   rows = (const int*)d_in[3];
    const int*   cols = (const int*)d_in[4];
    float*       out  = (float*)d_out;

    const int n_edges = in_sizes[3];

    const size_t smem = (size_t)SM_U32 * sizeof(uint32_t);
    cudaFuncSetAttribute(k_gemm, cudaFuncAttributeMaxDynamicSharedMemorySize,
                         (int)smem);

    k_place<<<(n_edges + 255) / 256, 256>>>(rows, cols, n_edges);

    const int gemm_blocks = (N_NODES + NPB - 1) / NPB;
    k_gemm<<<gemm_blocks, 512, smem>>>(x, W, b, out);

    const int gf_blocks = (N_NODES * 32 + 255) / 256;  // warp per node
    k_gather_final<<<gf_blocks, 256>>>(x, out);

    k_fix<<<16, 256>>>(x, out);
}